// round 2
// baseline (speedup 1.0000x reference)
#include <cuda_runtime.h>
#include <cstdint>

#define D_MODEL 1024
#define NHEAD   16
#define DH      64
#define BB      2
#define SS      2048
#define M_TOT   (BB*SS)        // 4096
#define QKV_N   (3*D_MODEL)    // 3072

// Scratch (static device arrays: allocation-free per harness rules)
__device__ float g_Q[BB*NHEAD*SS*DH];      // [B,H,S,dh]
__device__ float g_K[BB*NHEAD*SS*DH];
__device__ float g_V[BB*NHEAD*SS*DH];
__device__ float g_attn[M_TOT*D_MODEL];    // [B,S,D]

// ---------------------------------------------------------------------------
// Fast exp on the FMA pipe (avoids the MUFU rt=8 bottleneck: 134M exps would
// cost ~1.8M cycles on MUFU vs ~60K cycles as FMA polynomial).
// Valid for x <= 0 (softmax always has x <= 0); clamps at -87.
// ---------------------------------------------------------------------------
__device__ __forceinline__ float fast_exp(float x) {
    x = fmaxf(x, -87.0f);                       // also swallows -inf / NaN safely
    float z = fmaf(x, 1.442695041f, 12582912.0f); // round(x*log2e) into mantissa
    float n = z - 12582912.0f;
    float f = fmaf(x, 1.442695041f, -n);        // f in [-0.5, 0.5]
    float p = 0.0013333558f;
    p = fmaf(p, f, 0.0096181291f);
    p = fmaf(p, f, 0.0555041087f);
    p = fmaf(p, f, 0.2402265069f);
    p = fmaf(p, f, 0.6931471806f);
    p = fmaf(p, f, 1.0f);
    int zi = __float_as_int(z);
    float scale = __int_as_float((zi << 23) + 0x3F800000); // 2^n (n >= -126)
    return p * scale;
}

__device__ __forceinline__ float rmax16(float v) {
    v = fmaxf(v, __shfl_xor_sync(0xffffffffu, v, 1));
    v = fmaxf(v, __shfl_xor_sync(0xffffffffu, v, 2));
    v = fmaxf(v, __shfl_xor_sync(0xffffffffu, v, 4));
    v = fmaxf(v, __shfl_xor_sync(0xffffffffu, v, 8));
    return v;
}
__device__ __forceinline__ float rsum16(float v) {
    v += __shfl_xor_sync(0xffffffffu, v, 1);
    v += __shfl_xor_sync(0xffffffffu, v, 2);
    v += __shfl_xor_sync(0xffffffffu, v, 4);
    v += __shfl_xor_sync(0xffffffffu, v, 8);
    return v;
}

// ---------------------------------------------------------------------------
// QKV projection: X[4096,1024] @ Wqkv[1024,3072] + b, scattered into
// g_Q/g_K/g_V with [B,H,S,dh] layout. Classic 128x128x8 SGEMM, 8x8/thread.
// ---------------------------------------------------------------------------
__global__ __launch_bounds__(256) void qkv_gemm(const float* __restrict__ A,
                                                const float* __restrict__ Bw,
                                                const float* __restrict__ bias) {
    __shared__ float As[8][128];
    __shared__ float Bs[8][128];
    const int K = D_MODEL, N = QKV_N;
    int n0 = blockIdx.x * 128, m0 = blockIdx.y * 128;
    int tid = threadIdx.x;
    int tx = tid & 15, ty = tid >> 4;
    int arow = tid >> 1,  acol = (tid & 1) * 4;
    int brow = tid >> 5,  bcol = (tid & 31) * 4;

    const float* Ap = A  + (size_t)(m0 + arow) * K + acol;
    const float* Bp = Bw + (size_t)brow * N + n0 + bcol;

    float acc[8][8];
#pragma unroll
    for (int i = 0; i < 8; i++)
#pragma unroll
        for (int j = 0; j < 8; j++) acc[i][j] = 0.f;

    for (int k0 = 0; k0 < K; k0 += 8) {
        float4 a  = *(const float4*)Ap;  Ap += 8;
        float4 bv = *(const float4*)Bp;  Bp += (size_t)8 * N;
        As[acol + 0][arow] = a.x; As[acol + 1][arow] = a.y;
        As[acol + 2][arow] = a.z; As[acol + 3][arow] = a.w;
        *(float4*)&Bs[brow][bcol] = bv;
        __syncthreads();
#pragma unroll
        for (int kk = 0; kk < 8; kk++) {
            float ra[8], rb[8];
            *(float4*)(ra)     = *(float4*)&As[kk][ty * 8];
            *(float4*)(ra + 4) = *(float4*)&As[kk][ty * 8 + 4];
            *(float4*)(rb)     = *(float4*)&Bs[kk][tx * 8];
            *(float4*)(rb + 4) = *(float4*)&Bs[kk][tx * 8 + 4];
#pragma unroll
            for (int i = 0; i < 8; i++)
#pragma unroll
                for (int j = 0; j < 8; j++)
                    acc[i][j] = fmaf(ra[i], rb[j], acc[i][j]);
        }
        __syncthreads();
    }

    // Scatter epilogue: columns [n0+tx*8, +8) stay within one q/k/v and one head
    int nb  = n0 + tx * 8;
    int sel = nb >> 10;
    int d   = nb & 1023;
    int h   = d >> 6, dd = d & 63;
    float* dst = (sel == 0) ? g_Q : ((sel == 1) ? g_K : g_V);
    float4 b0 = *(const float4*)(bias + nb);
    float4 b1 = *(const float4*)(bias + nb + 4);
#pragma unroll
    for (int i = 0; i < 8; i++) {
        int mm = m0 + ty * 8 + i;
        int bb = mm >> 11, ss = mm & 2047;
        float* p = dst + (((size_t)(bb * NHEAD + h) * SS + ss) * DH + dd);
        float4 v0 = make_float4(acc[i][0] + b0.x, acc[i][1] + b0.y,
                                acc[i][2] + b0.z, acc[i][3] + b0.w);
        float4 v1 = make_float4(acc[i][4] + b1.x, acc[i][5] + b1.y,
                                acc[i][6] + b1.z, acc[i][7] + b1.w);
        *(float4*)p       = v0;
        *(float4*)(p + 4) = v1;
    }
}

// ---------------------------------------------------------------------------
// Flash attention: one block per (64-row q-tile, b*h). 256 threads as 16x16;
// thread = (tr, tc): 4 q-rows x 4 keys for scores, 4 q-rows x 4 dims for O.
// XOR swizzle (dv ^ row>>2) on Q/K/V tiles for conflict-free float4 LDS.
// ---------------------------------------------------------------------------
__global__ __launch_bounds__(256) void attn_kernel(const int* __restrict__ mask) {
    extern __shared__ float sm[];
    float* Qs  = sm;
    float* Ks  = sm + 64 * 64;
    float* Vs  = sm + 2 * 64 * 64;
    float* Ps  = sm + 3 * 64 * 64;
    float* mks = sm + 4 * 64 * 64;   // 64 floats: 0 or -inf per key

    int qt = blockIdx.x, bh = blockIdx.y;
    int b = bh >> 4, h = bh & 15;
    const float* Qg = g_Q + ((size_t)bh * SS + qt * 64) * DH;
    const float* Kg = g_K + (size_t)bh * SS * DH;
    const float* Vg = g_V + (size_t)bh * SS * DH;

    int tid = threadIdx.x;
    int tc = tid & 15, tr = tid >> 4;

    // Load Q tile (swizzled)
#pragma unroll
    for (int it = 0; it < 4; it++) {
        int i = tid + it * 256;
        int row = i >> 4, dv = i & 15;
        int sw = (dv ^ ((row >> 2) & 15)) * 4;
        *(float4*)(Qs + row * 64 + sw) = *(const float4*)(Qg + row * 64 + dv * 4);
    }

    float m[4], l[4];
    float4 O[4];
#pragma unroll
    for (int i = 0; i < 4; i++) { m[i] = -INFINITY; l[i] = 0.f; O[i] = make_float4(0.f,0.f,0.f,0.f); }

    for (int kt = 0; kt < SS / 64; kt++) {
        __syncthreads();   // prior-iteration smem reads done
#pragma unroll
        for (int it = 0; it < 4; it++) {
            int i = tid + it * 256;
            int row = i >> 4, dv = i & 15;
            int sw = (dv ^ ((row >> 2) & 15)) * 4;
            *(float4*)(Ks + row * 64 + sw) = *(const float4*)(Kg + (kt * 64 + row) * 64 + dv * 4);
            *(float4*)(Vs + row * 64 + sw) = *(const float4*)(Vg + (kt * 64 + row) * 64 + dv * 4);
        }
        if (tid < 64)
            mks[tid] = (mask[b * SS + kt * 64 + tid] != 0) ? 0.f : -INFINITY;
        __syncthreads();

        // ---- scores: sc[i][j] = Q[4tr+i] . K[4tc+j] ----
        float sc[4][4];
#pragma unroll
        for (int i = 0; i < 4; i++)
#pragma unroll
            for (int j = 0; j < 4; j++) sc[i][j] = 0.f;

#pragma unroll
        for (int dv = 0; dv < 16; dv++) {
            float4 q[4];
            int qsw = (dv ^ tr) * 4;
#pragma unroll
            for (int i = 0; i < 4; i++)
                q[i] = *(float4*)(Qs + (4 * tr + i) * 64 + qsw);
            int ksw = (dv ^ tc) * 4;
#pragma unroll
            for (int j = 0; j < 4; j++) {
                float4 kk = *(float4*)(Ks + (4 * tc + j) * 64 + ksw);
#pragma unroll
                for (int i = 0; i < 4; i++) {
                    sc[i][j] = fmaf(q[i].x, kk.x, sc[i][j]);
                    sc[i][j] = fmaf(q[i].y, kk.y, sc[i][j]);
                    sc[i][j] = fmaf(q[i].z, kk.z, sc[i][j]);
                    sc[i][j] = fmaf(q[i].w, kk.w, sc[i][j]);
                }
            }
        }

        float mkc[4];
#pragma unroll
        for (int j = 0; j < 4; j++) mkc[j] = mks[4 * tc + j];
#pragma unroll
        for (int i = 0; i < 4; i++)
#pragma unroll
            for (int j = 0; j < 4; j++)
                sc[i][j] = fmaf(sc[i][j], 0.125f, mkc[j]);   // 1/sqrt(64)

        // ---- online softmax (row groups = 16 lanes sharing tr) ----
#pragma unroll
        for (int i = 0; i < 4; i++) {
            float rm = fmaxf(fmaxf(sc[i][0], sc[i][1]), fmaxf(sc[i][2], sc[i][3]));
            rm = rmax16(rm);
            float mnew = fmaxf(m[i], rm);
            float corr = fast_exp(m[i] - mnew);
            m[i] = mnew;
            float4 pv;
            pv.x = fast_exp(sc[i][0] - mnew);
            pv.y = fast_exp(sc[i][1] - mnew);
            pv.z = fast_exp(sc[i][2] - mnew);
            pv.w = fast_exp(sc[i][3] - mnew);
            *(float4*)(Ps + (4 * tr + i) * 64 + 4 * tc) = pv;
            float rs = rsum16(pv.x + pv.y + pv.z + pv.w);
            l[i] = l[i] * corr + rs;
            O[i].x *= corr; O[i].y *= corr; O[i].z *= corr; O[i].w *= corr;
        }
        __syncthreads();

        // ---- O += P @ V  (thread owns dims 4tc..4tc+3) ----
#pragma unroll 4
        for (int k = 0; k < 64; k++) {
            float4 v = *(const float4*)(Vs + k * 64 + ((tc ^ ((k >> 2) & 15)) * 4));
#pragma unroll
            for (int i = 0; i < 4; i++) {
                float p = Ps[(4 * tr + i) * 64 + k];
                O[i].x = fmaf(p, v.x, O[i].x);
                O[i].y = fmaf(p, v.y, O[i].y);
                O[i].z = fmaf(p, v.z, O[i].z);
                O[i].w = fmaf(p, v.w, O[i].w);
            }
        }
    }

    // epilogue -> g_attn [B,S,D]
#pragma unroll
    for (int i = 0; i < 4; i++) {
        float inv = 1.0f / l[i];
        float4 o = make_float4(O[i].x * inv, O[i].y * inv, O[i].z * inv, O[i].w * inv);
        int row = qt * 64 + 4 * tr + i;
        *(float4*)(g_attn + ((size_t)b * SS + row) * D_MODEL + h * DH + 4 * tc) = o;
    }
}

// ---------------------------------------------------------------------------
// Output projection: g_attn[4096,1024] @ Wout[1024,1024] + b -> d_out
// ---------------------------------------------------------------------------
__global__ __launch_bounds__(256) void out_gemm(const float* __restrict__ Bw,
                                                const float* __restrict__ bias,
                                                float* __restrict__ C) {
    __shared__ float As[8][128];
    __shared__ float Bs[8][128];
    const int K = D_MODEL, N = D_MODEL;
    int n0 = blockIdx.x * 128, m0 = blockIdx.y * 128;
    int tid = threadIdx.x;
    int tx = tid & 15, ty = tid >> 4;
    int arow = tid >> 1,  acol = (tid & 1) * 4;
    int brow = tid >> 5,  bcol = (tid & 31) * 4;

    const float* Ap = g_attn + (size_t)(m0 + arow) * K + acol;
    const float* Bp = Bw + (size_t)brow * N + n0 + bcol;

    float acc[8][8];
#pragma unroll
    for (int i = 0; i < 8; i++)
#pragma unroll
        for (int j = 0; j < 8; j++) acc[i][j] = 0.f;

    for (int k0 = 0; k0 < K; k0 += 8) {
        float4 a  = *(const float4*)Ap;  Ap += 8;
        float4 bv = *(const float4*)Bp;  Bp += (size_t)8 * N;
        As[acol + 0][arow] = a.x; As[acol + 1][arow] = a.y;
        As[acol + 2][arow] = a.z; As[acol + 3][arow] = a.w;
        *(float4*)&Bs[brow][bcol] = bv;
        __syncthreads();
#pragma unroll
        for (int kk = 0; kk < 8; kk++) {
            float ra[8], rb[8];
            *(float4*)(ra)     = *(float4*)&As[kk][ty * 8];
            *(float4*)(ra + 4) = *(float4*)&As[kk][ty * 8 + 4];
            *(float4*)(rb)     = *(float4*)&Bs[kk][tx * 8];
            *(float4*)(rb + 4) = *(float4*)&Bs[kk][tx * 8 + 4];
#pragma unroll
            for (int i = 0; i < 8; i++)
#pragma unroll
                for (int j = 0; j < 8; j++)
                    acc[i][j] = fmaf(ra[i], rb[j], acc[i][j]);
        }
        __syncthreads();
    }

    int nb = n0 + tx * 8;
    float4 b0 = *(const float4*)(bias + nb);
    float4 b1 = *(const float4*)(bias + nb + 4);
#pragma unroll
    for (int i = 0; i < 8; i++) {
        int mm = m0 + ty * 8 + i;
        float* p = C + (size_t)mm * N + nb;
        float4 v0 = make_float4(acc[i][0] + b0.x, acc[i][1] + b0.y,
                                acc[i][2] + b0.z, acc[i][3] + b0.w);
        float4 v1 = make_float4(acc[i][4] + b1.x, acc[i][5] + b1.y,
                                acc[i][6] + b1.z, acc[i][7] + b1.w);
        *(float4*)p       = v0;
        *(float4*)(p + 4) = v1;
    }
}

extern "C" void kernel_launch(void* const* d_in, const int* in_sizes, int n_in,
                              void* d_out, int out_size) {
    const float* x    = (const float*)d_in[0];
    const int*   mask = (const int*)d_in[1];     // bool exported as int32
    const float* Wqkv = (const float*)d_in[2];
    const float* bqkv = (const float*)d_in[3];
    const float* Wout = (const float*)d_in[4];
    const float* bout = (const float*)d_in[5];
    float*       out  = (float*)d_out;

    qkv_gemm<<<dim3(QKV_N / 128, M_TOT / 128), 256>>>(x, Wqkv, bqkv);

    const int SMEM = (4 * 64 * 64 + 64) * (int)sizeof(float);  // ~65.8 KB
    cudaFuncSetAttribute(attn_kernel, cudaFuncAttributeMaxDynamicSharedMemorySize, SMEM);
    attn_kernel<<<dim3(SS / 64, BB * NHEAD), 256, SMEM>>>(mask);

    out_gemm<<<dim3(D_MODEL / 128, M_TOT / 128), 256>>>(Wout, bout, out);
}

// round 4
// speedup vs baseline: 1.3810x; 1.3810x over previous
#include <cuda_runtime.h>
#include <cuda_bf16.h>
#include <cstdint>

#define D_MODEL 1024
#define NHEAD   16
#define DH      64
#define BB      2
#define SS      2048
#define M_TOT   (BB*SS)        // 4096
#define QKV_N   (3*D_MODEL)    // 3072

// ---------------- scratch (static device arrays) ----------------
__device__ float g_Q[BB*NHEAD*SS*DH];
__device__ float g_K[BB*NHEAD*SS*DH];
__device__ float g_V[BB*NHEAD*SS*DH];
__device__ float g_attn[M_TOT*D_MODEL];
__device__ __nv_bfloat16 g_Wqkv_hi[QKV_N*D_MODEL];   // [N,K] transposed
__device__ __nv_bfloat16 g_Wqkv_lo[QKV_N*D_MODEL];
__device__ __nv_bfloat16 g_Wout_hi[D_MODEL*D_MODEL];
__device__ __nv_bfloat16 g_Wout_lo[D_MODEL*D_MODEL];

// ---------------- helpers ----------------
__device__ __forceinline__ uint32_t smem_to_u32(const void* p) {
    uint32_t a;
    asm("{ .reg .u64 t; cvta.to.shared.u64 t, %1; cvt.u32.u64 %0, t; }" : "=r"(a) : "l"(p));
    return a;
}
__device__ __forceinline__ uint32_t bf2u(__nv_bfloat162 v) {
    return *reinterpret_cast<uint32_t*>(&v);
}

#define LDSM_X4(r0,r1,r2,r3, addr) \
    asm volatile("ldmatrix.sync.aligned.m8n8.x4.shared.b16 {%0,%1,%2,%3}, [%4];" \
        : "=r"(r0),"=r"(r1),"=r"(r2),"=r"(r3) : "r"(addr))

#define MMA_BF16(d, a, b0, b1) \
    asm volatile("mma.sync.aligned.m16n8k16.row.col.f32.bf16.bf16.f32 " \
        "{%0,%1,%2,%3}, {%4,%5,%6,%7}, {%8,%9}, {%0,%1,%2,%3};" \
        : "+f"((d)[0]),"+f"((d)[1]),"+f"((d)[2]),"+f"((d)[3]) \
        : "r"((a)[0]),"r"((a)[1]),"r"((a)[2]),"r"((a)[3]), "r"(b0),"r"(b1))

// ---------------------------------------------------------------------------
// Prep: W[K,N] fp32 -> Whi/Wlo[N,K] bf16 (transpose + hi/lo split)
// ---------------------------------------------------------------------------
__global__ __launch_bounds__(256) void split_w(const float* __restrict__ W,
                                               __nv_bfloat16* __restrict__ Whi,
                                               __nv_bfloat16* __restrict__ Wlo,
                                               int K, int N) {
    __shared__ float t[32][33];
    int n0 = blockIdx.x * 32, k0 = blockIdx.y * 32;
    int tx = threadIdx.x & 31, ty = threadIdx.x >> 5;
#pragma unroll
    for (int i = 0; i < 4; i++)
        t[ty + 8 * i][tx] = W[(size_t)(k0 + ty + 8 * i) * N + n0 + tx];
    __syncthreads();
#pragma unroll
    for (int i = 0; i < 4; i++) {
        int n = ty + 8 * i;
        float v = t[tx][n];
        __nv_bfloat16 hi = __float2bfloat16_rn(v);
        __nv_bfloat16 lo = __float2bfloat16_rn(v - __bfloat162float(hi));
        Whi[(size_t)(n0 + n) * K + k0 + tx] = hi;
        Wlo[(size_t)(n0 + n) * K + k0 + tx] = lo;
    }
}

// ---------------------------------------------------------------------------
// mma.sync GEMM: C[M,N] = A[M,1024]fp32 @ Bt[N,1024](hi+lo bf16) + bias
// CTA 128x128, kc=32, warp grid 2x4 (warp tile 64x32), m16n8k16 bf16,
// 3-MMA hi/lo split. Smem rows pitch 80B (conflict-free ldmatrix, no swizzle).
// MODE 0: scatter into g_Q/g_K/g_V.  MODE 1: linear store to Cout.
// ---------------------------------------------------------------------------
#define KC 32
#define PITCH 80                       // bytes per smem row (40 bf16)
#define TILE_BYTES (128 * PITCH)       // 10240
#define BUF_BYTES (4 * TILE_BYTES)     // Ahi, Alo, Bhi, Blo
#define GEMM_SMEM (2 * BUF_BYTES)      // 81920

template<int MODE>
__global__ __launch_bounds__(256) void mma_gemm(
    const float* __restrict__ A,
    const __nv_bfloat16* __restrict__ Bhi,
    const __nv_bfloat16* __restrict__ Blo,
    const float* __restrict__ bias,
    float* __restrict__ Cout) {
    extern __shared__ char smem[];
    uint32_t smem_u = smem_to_u32(smem);
    int tid = threadIdx.x, wid = tid >> 5, lane = tid & 31;
    int m0 = blockIdx.y * 128, n0 = blockIdx.x * 128;
    int wm = (wid >> 2) * 64;   // warp row offset (0 / 64)
    int wn = (wid & 3) * 32;    // warp col offset

    const int NCH = D_MODEL / KC;   // 32

    // prefetch registers
    float4 pa[2][2];   // A: [it][2x float4 = 8 k]
    uint4  pbh[2], pbl[2];
    int arow[2], au[2], brow[2], bu[2];
#pragma unroll
    for (int it = 0; it < 2; it++) {
        int idx = tid + it * 256;
        arow[it] = idx >> 2; au[it] = idx & 3;
        brow[it] = idx >> 2; bu[it] = idx & 3;
    }

    auto ldg_chunk = [&](int c) {
        int k0 = c * KC;
#pragma unroll
        for (int it = 0; it < 2; it++) {
            const float* ap = A + (size_t)(m0 + arow[it]) * D_MODEL + k0 + au[it] * 8;
            pa[it][0] = *(const float4*)ap;
            pa[it][1] = *(const float4*)(ap + 4);
            pbh[it] = *(const uint4*)(Bhi + (size_t)(n0 + brow[it]) * D_MODEL + k0 + bu[it] * 8);
            pbl[it] = *(const uint4*)(Blo + (size_t)(n0 + brow[it]) * D_MODEL + k0 + bu[it] * 8);
        }
    };
    auto sts_chunk = [&](int buf) {
        char* base = smem + buf * BUF_BYTES;
#pragma unroll
        for (int it = 0; it < 2; it++) {
            float4 x0 = pa[it][0], x1 = pa[it][1];
            __nv_bfloat162 h01 = __floats2bfloat162_rn(x0.x, x0.y);
            __nv_bfloat162 h23 = __floats2bfloat162_rn(x0.z, x0.w);
            __nv_bfloat162 h45 = __floats2bfloat162_rn(x1.x, x1.y);
            __nv_bfloat162 h67 = __floats2bfloat162_rn(x1.z, x1.w);
            __nv_bfloat162 l01 = __floats2bfloat162_rn(x0.x - __low2float(h01), x0.y - __high2float(h01));
            __nv_bfloat162 l23 = __floats2bfloat162_rn(x0.z - __low2float(h23), x0.w - __high2float(h23));
            __nv_bfloat162 l45 = __floats2bfloat162_rn(x1.x - __low2float(h45), x1.y - __high2float(h45));
            __nv_bfloat162 l67 = __floats2bfloat162_rn(x1.z - __low2float(h67), x1.w - __high2float(h67));
            uint32_t off = arow[it] * PITCH + au[it] * 16;
            *(uint4*)(base + off) = make_uint4(bf2u(h01), bf2u(h23), bf2u(h45), bf2u(h67));
            *(uint4*)(base + TILE_BYTES + off) = make_uint4(bf2u(l01), bf2u(l23), bf2u(l45), bf2u(l67));
            uint32_t boff = brow[it] * PITCH + bu[it] * 16;
            *(uint4*)(base + 2 * TILE_BYTES + boff) = pbh[it];
            *(uint4*)(base + 3 * TILE_BYTES + boff) = pbl[it];
        }
    };

    float acc[4][4][4];
#pragma unroll
    for (int i = 0; i < 4; i++)
#pragma unroll
        for (int j = 0; j < 4; j++)
#pragma unroll
            for (int r = 0; r < 4; r++) acc[i][j][r] = 0.f;

    ldg_chunk(0);
    sts_chunk(0);
    __syncthreads();

    int alr = lane & 15, alu = lane >> 4;                 // A ldmatrix lane map
    int blr = (lane & 7) + ((lane >> 4) << 3);            // B row within 16
    int blu = (lane >> 3) & 1;                            // B k-unit select

    for (int c = 0; c < NCH; c++) {
        if (c + 1 < NCH) ldg_chunk(c + 1);

        uint32_t sA = smem_u + (c & 1) * BUF_BYTES;
        uint32_t sB = sA + 2 * TILE_BYTES;
#pragma unroll
        for (int ks = 0; ks < 2; ks++) {
            uint32_t ah[4][4], al[4][4], bh[4][2], bl[4][2];
#pragma unroll
            for (int fm = 0; fm < 4; fm++) {
                uint32_t ad = sA + (wm + fm * 16 + alr) * PITCH + (ks * 2 + alu) * 16;
                LDSM_X4(ah[fm][0], ah[fm][1], ah[fm][2], ah[fm][3], ad);
                LDSM_X4(al[fm][0], al[fm][1], al[fm][2], al[fm][3], ad + TILE_BYTES);
            }
#pragma unroll
            for (int fp = 0; fp < 2; fp++) {
                uint32_t bd = sB + (wn + fp * 16 + blr) * PITCH + (ks * 2 + blu) * 16;
                uint32_t r0, r1, r2, r3;
                LDSM_X4(r0, r1, r2, r3, bd);
                bh[fp * 2][0] = r0; bh[fp * 2][1] = r1;
                bh[fp * 2 + 1][0] = r2; bh[fp * 2 + 1][1] = r3;
                LDSM_X4(r0, r1, r2, r3, bd + TILE_BYTES);
                bl[fp * 2][0] = r0; bl[fp * 2][1] = r1;
                bl[fp * 2 + 1][0] = r2; bl[fp * 2 + 1][1] = r3;
            }
#pragma unroll
            for (int fm = 0; fm < 4; fm++)
#pragma unroll
                for (int fn = 0; fn < 4; fn++) {
                    MMA_BF16(acc[fm][fn], ah[fm], bh[fn][0], bh[fn][1]);
                    MMA_BF16(acc[fm][fn], ah[fm], bl[fn][0], bl[fn][1]);
                    MMA_BF16(acc[fm][fn], al[fm], bh[fn][0], bh[fn][1]);
                }
        }
        __syncthreads();
        if (c + 1 < NCH) {
            sts_chunk((c + 1) & 1);
            __syncthreads();
        }
    }

    // ---- epilogue ----
#pragma unroll
    for (int fm = 0; fm < 4; fm++)
#pragma unroll
        for (int fn = 0; fn < 4; fn++) {
            int gn = n0 + wn + fn * 8 + (lane & 3) * 2;
            float bx = bias[gn], by = bias[gn + 1];
#pragma unroll
            for (int half = 0; half < 2; half++) {
                int gm = m0 + wm + fm * 16 + (lane >> 2) + half * 8;
                float2 v = make_float2(acc[fm][fn][half * 2] + bx,
                                       acc[fm][fn][half * 2 + 1] + by);
                if (MODE == 0) {
                    int bb = gm >> 11, ssi = gm & 2047;
                    int sel = gn >> 10, d = gn & 1023;
                    int h = d >> 6, dd = d & 63;
                    float* dst = (sel == 0) ? g_Q : ((sel == 1) ? g_K : g_V);
                    *(float2*)(dst + (((size_t)(bb * NHEAD + h) * SS + ssi) * DH + dd)) = v;
                } else {
                    *(float2*)(Cout + (size_t)gm * D_MODEL + gn) = v;
                }
            }
        }
}

// ---------------------------------------------------------------------------
// fast exp on FMA pipe (x <= 0)
// ---------------------------------------------------------------------------
__device__ __forceinline__ float fast_exp(float x) {
    x = fmaxf(x, -87.0f);
    float z = fmaf(x, 1.442695041f, 12582912.0f);
    float n = z - 12582912.0f;
    float f = fmaf(x, 1.442695041f, -n);
    float p = 0.0013333558f;
    p = fmaf(p, f, 0.0096181291f);
    p = fmaf(p, f, 0.0555041087f);
    p = fmaf(p, f, 0.2402265069f);
    p = fmaf(p, f, 0.6931471806f);
    p = fmaf(p, f, 1.0f);
    int zi = __float_as_int(z);
    float scale = __int_as_float((zi << 23) + 0x3F800000);
    return p * scale;
}
__device__ __forceinline__ float rmax16(float v) {
    v = fmaxf(v, __shfl_xor_sync(0xffffffffu, v, 1));
    v = fmaxf(v, __shfl_xor_sync(0xffffffffu, v, 2));
    v = fmaxf(v, __shfl_xor_sync(0xffffffffu, v, 4));
    v = fmaxf(v, __shfl_xor_sync(0xffffffffu, v, 8));
    return v;
}
__device__ __forceinline__ float rsum16(float v) {
    v += __shfl_xor_sync(0xffffffffu, v, 1);
    v += __shfl_xor_sync(0xffffffffu, v, 2);
    v += __shfl_xor_sync(0xffffffffu, v, 4);
    v += __shfl_xor_sync(0xffffffffu, v, 8);
    return v;
}

// ---------------------------------------------------------------------------
// Flash attention (SIMT fp32) — unchanged from the passing round-2 kernel.
// ---------------------------------------------------------------------------
__global__ __launch_bounds__(256) void attn_kernel(const int* __restrict__ mask) {
    extern __shared__ float smf[];
    float* Qs  = smf;
    float* Ks  = smf + 64 * 64;
    float* Vs  = smf + 2 * 64 * 64;
    float* Ps  = smf + 3 * 64 * 64;
    float* mks = smf + 4 * 64 * 64;

    int qt = blockIdx.x, bh = blockIdx.y;
    int b = bh >> 4;
    int h = bh & 15;
    const float* Qg = g_Q + ((size_t)bh * SS + qt * 64) * DH;
    const float* Kg = g_K + (size_t)bh * SS * DH;
    const float* Vg = g_V + (size_t)bh * SS * DH;

    int tid = threadIdx.x;
    int tc = tid & 15, tr = tid >> 4;

#pragma unroll
    for (int it = 0; it < 4; it++) {
        int i = tid + it * 256;
        int row = i >> 4, dv = i & 15;
        int sw = (dv ^ ((row >> 2) & 15)) * 4;
        *(float4*)(Qs + row * 64 + sw) = *(const float4*)(Qg + row * 64 + dv * 4);
    }

    float m[4], l[4];
    float4 O[4];
#pragma unroll
    for (int i = 0; i < 4; i++) { m[i] = -INFINITY; l[i] = 0.f; O[i] = make_float4(0.f,0.f,0.f,0.f); }

    for (int kt = 0; kt < SS / 64; kt++) {
        __syncthreads();
#pragma unroll
        for (int it = 0; it < 4; it++) {
            int i = tid + it * 256;
            int row = i >> 4, dv = i & 15;
            int sw = (dv ^ ((row >> 2) & 15)) * 4;
            *(float4*)(Ks + row * 64 + sw) = *(const float4*)(Kg + (kt * 64 + row) * 64 + dv * 4);
            *(float4*)(Vs + row * 64 + sw) = *(const float4*)(Vg + (kt * 64 + row) * 64 + dv * 4);
        }
        if (tid < 64)
            mks[tid] = (mask[b * SS + kt * 64 + tid] != 0) ? 0.f : -INFINITY;
        __syncthreads();

        float sc[4][4];
#pragma unroll
        for (int i = 0; i < 4; i++)
#pragma unroll
            for (int j = 0; j < 4; j++) sc[i][j] = 0.f;

#pragma unroll
        for (int dv = 0; dv < 16; dv++) {
            float4 q[4];
            int qsw = (dv ^ tr) * 4;
#pragma unroll
            for (int i = 0; i < 4; i++)
                q[i] = *(float4*)(Qs + (4 * tr + i) * 64 + qsw);
            int ksw = (dv ^ tc) * 4;
#pragma unroll
            for (int j = 0; j < 4; j++) {
                float4 kk = *(float4*)(Ks + (4 * tc + j) * 64 + ksw);
#pragma unroll
                for (int i = 0; i < 4; i++) {
                    sc[i][j] = fmaf(q[i].x, kk.x, sc[i][j]);
                    sc[i][j] = fmaf(q[i].y, kk.y, sc[i][j]);
                    sc[i][j] = fmaf(q[i].z, kk.z, sc[i][j]);
                    sc[i][j] = fmaf(q[i].w, kk.w, sc[i][j]);
                }
            }
        }

        float mkc[4];
#pragma unroll
        for (int j = 0; j < 4; j++) mkc[j] = mks[4 * tc + j];
#pragma unroll
        for (int i = 0; i < 4; i++)
#pragma unroll
            for (int j = 0; j < 4; j++)
                sc[i][j] = fmaf(sc[i][j], 0.125f, mkc[j]);

#pragma unroll
        for (int i = 0; i < 4; i++) {
            float rm = fmaxf(fmaxf(sc[i][0], sc[i][1]), fmaxf(sc[i][2], sc[i][3]));
            rm = rmax16(rm);
            float mnew = fmaxf(m[i], rm);
            float corr = fast_exp(m[i] - mnew);
            m[i] = mnew;
            float4 pv;
            pv.x = fast_exp(sc[i][0] - mnew);
            pv.y = fast_exp(sc[i][1] - mnew);
            pv.z = fast_exp(sc[i][2] - mnew);
            pv.w = fast_exp(sc[i][3] - mnew);
            *(float4*)(Ps + (4 * tr + i) * 64 + 4 * tc) = pv;
            float rs = rsum16(pv.x + pv.y + pv.z + pv.w);
            l[i] = l[i] * corr + rs;
            O[i].x *= corr; O[i].y *= corr; O[i].z *= corr; O[i].w *= corr;
        }
        __syncthreads();

#pragma unroll 4
        for (int k = 0; k < 64; k++) {
            float4 v = *(const float4*)(Vs + k * 64 + ((tc ^ ((k >> 2) & 15)) * 4));
#pragma unroll
            for (int i = 0; i < 4; i++) {
                float p = Ps[(4 * tr + i) * 64 + k];
                O[i].x = fmaf(p, v.x, O[i].x);
                O[i].y = fmaf(p, v.y, O[i].y);
                O[i].z = fmaf(p, v.z, O[i].z);
                O[i].w = fmaf(p, v.w, O[i].w);
            }
        }
    }

#pragma unroll
    for (int i = 0; i < 4; i++) {
        float inv = 1.0f / l[i];
        float4 o = make_float4(O[i].x * inv, O[i].y * inv, O[i].z * inv, O[i].w * inv);
        int row = qt * 64 + 4 * tr + i;
        *(float4*)(g_attn + ((size_t)b * SS + row) * D_MODEL + h * DH + 4 * tc) = o;
    }
}

extern "C" void kernel_launch(void* const* d_in, const int* in_sizes, int n_in,
                              void* d_out, int out_size) {
    const float* x    = (const float*)d_in[0];
    const int*   mask = (const int*)d_in[1];
    const float* Wqkv = (const float*)d_in[2];
    const float* bqkv = (const float*)d_in[3];
    const float* Wout = (const float*)d_in[4];
    const float* bout = (const float*)d_in[5];
    float*       out  = (float*)d_out;

    __nv_bfloat16 *wqh, *wql, *woh, *wol;
    cudaGetSymbolAddress((void**)&wqh, g_Wqkv_hi);
    cudaGetSymbolAddress((void**)&wql, g_Wqkv_lo);
    cudaGetSymbolAddress((void**)&woh, g_Wout_hi);
    cudaGetSymbolAddress((void**)&wol, g_Wout_lo);
    float* gattn;
    cudaGetSymbolAddress((void**)&gattn, g_attn);

    // 1) weight transpose + bf16 hi/lo split
    split_w<<<dim3(QKV_N / 32, D_MODEL / 32), 256>>>(Wqkv, wqh, wql, D_MODEL, QKV_N);
    split_w<<<dim3(D_MODEL / 32, D_MODEL / 32), 256>>>(Wout, woh, wol, D_MODEL, D_MODEL);

    // 2) QKV projection on tensor cores (mma.sync)
    cudaFuncSetAttribute(mma_gemm<0>, cudaFuncAttributeMaxDynamicSharedMemorySize, GEMM_SMEM);
    cudaFuncSetAttribute(mma_gemm<1>, cudaFuncAttributeMaxDynamicSharedMemorySize, GEMM_SMEM);
    mma_gemm<0><<<dim3(QKV_N / 128, M_TOT / 128), 256, GEMM_SMEM>>>(x, wqh, wql, bqkv, nullptr);

    // 3) attention (SIMT fp32)
    const int SMEM = (4 * 64 * 64 + 64) * (int)sizeof(float);
    cudaFuncSetAttribute(attn_kernel, cudaFuncAttributeMaxDynamicSharedMemorySize, SMEM);
    attn_kernel<<<dim3(SS / 64, BB * NHEAD), 256, SMEM>>>(mask);

    // 4) output projection on tensor cores (mma.sync)
    mma_gemm<1><<<dim3(D_MODEL / 128, M_TOT / 128), 256, GEMM_SMEM>>>(gattn, woh, wol, bout, out);
}

// round 5
// speedup vs baseline: 2.5515x; 1.8475x over previous
#include <cuda_runtime.h>
#include <cuda_bf16.h>
#include <cstdint>

#define D_MODEL 1024
#define NHEAD   16
#define DH      64
#define BB      2
#define SS      2048
#define M_TOT   (BB*SS)        // 4096
#define QKV_N   (3*D_MODEL)    // 3072

// ---------------- scratch (static device arrays) ----------------
__device__ float g_attn[M_TOT*D_MODEL];
__device__ float g_maskf[BB*SS];
__device__ __nv_bfloat16 g_Qh[BB*NHEAD*SS*DH], g_Ql[BB*NHEAD*SS*DH];
__device__ __nv_bfloat16 g_Kh[BB*NHEAD*SS*DH], g_Kl[BB*NHEAD*SS*DH];
__device__ __nv_bfloat16 g_Vh[BB*NHEAD*SS*DH], g_Vl[BB*NHEAD*SS*DH];
__device__ __nv_bfloat16 g_Wqkv_hi[QKV_N*D_MODEL];
__device__ __nv_bfloat16 g_Wqkv_lo[QKV_N*D_MODEL];
__device__ __nv_bfloat16 g_Wout_hi[D_MODEL*D_MODEL];
__device__ __nv_bfloat16 g_Wout_lo[D_MODEL*D_MODEL];

// ---------------- helpers ----------------
__device__ __forceinline__ uint32_t smem_to_u32(const void* p) {
    uint32_t a;
    asm("{ .reg .u64 t; cvta.to.shared.u64 t, %1; cvt.u32.u64 %0, t; }" : "=r"(a) : "l"(p));
    return a;
}
__device__ __forceinline__ uint32_t bf2u(__nv_bfloat162 v) {
    return *reinterpret_cast<uint32_t*>(&v);
}

#define LDSM_X4(r0,r1,r2,r3, addr) \
    asm volatile("ldmatrix.sync.aligned.m8n8.x4.shared.b16 {%0,%1,%2,%3}, [%4];" \
        : "=r"(r0),"=r"(r1),"=r"(r2),"=r"(r3) : "r"(addr))

#define LDSM_X4_T(r0,r1,r2,r3, addr) \
    asm volatile("ldmatrix.sync.aligned.m8n8.x4.trans.shared.b16 {%0,%1,%2,%3}, [%4];" \
        : "=r"(r0),"=r"(r1),"=r"(r2),"=r"(r3) : "r"(addr))

#define MMA_BF16(d, a, b0, b1) \
    asm volatile("mma.sync.aligned.m16n8k16.row.col.f32.bf16.bf16.f32 " \
        "{%0,%1,%2,%3}, {%4,%5,%6,%7}, {%8,%9}, {%0,%1,%2,%3};" \
        : "+f"((d)[0]),"+f"((d)[1]),"+f"((d)[2]),"+f"((d)[3]) \
        : "r"((a)[0]),"r"((a)[1]),"r"((a)[2]),"r"((a)[3]), "r"(b0),"r"(b1))

#define CP_ASYNC16(sa, ga) \
    asm volatile("cp.async.cg.shared.global [%0], [%1], 16;" :: "r"(sa), "l"(ga))
#define CP_COMMIT() asm volatile("cp.async.commit_group;")
#define CP_WAIT1()  asm volatile("cp.async.wait_group 1;")

__device__ __forceinline__ float fast_exp(float x) {
    x = fmaxf(x, -87.0f);
    float z = fmaf(x, 1.442695041f, 12582912.0f);
    float n = z - 12582912.0f;
    float f = fmaf(x, 1.442695041f, -n);
    float p = 0.0013333558f;
    p = fmaf(p, f, 0.0096181291f);
    p = fmaf(p, f, 0.0555041087f);
    p = fmaf(p, f, 0.2402265069f);
    p = fmaf(p, f, 0.6931471806f);
    p = fmaf(p, f, 1.0f);
    int zi = __float_as_int(z);
    float scale = __int_as_float((zi << 23) + 0x3F800000);
    return p * scale;
}

// ---------------------------------------------------------------------------
// Prep: W[K,N] fp32 -> Whi/Wlo[N,K] bf16 (transpose + hi/lo split)
// ---------------------------------------------------------------------------
__global__ __launch_bounds__(256) void split_w(const float* __restrict__ W,
                                               __nv_bfloat16* __restrict__ Whi,
                                               __nv_bfloat16* __restrict__ Wlo,
                                               int K, int N) {
    __shared__ float t[32][33];
    int n0 = blockIdx.x * 32, k0 = blockIdx.y * 32;
    int tx = threadIdx.x & 31, ty = threadIdx.x >> 5;
#pragma unroll
    for (int i = 0; i < 4; i++)
        t[ty + 8 * i][tx] = W[(size_t)(k0 + ty + 8 * i) * N + n0 + tx];
    __syncthreads();
#pragma unroll
    for (int i = 0; i < 4; i++) {
        int n = ty + 8 * i;
        float v = t[tx][n];
        __nv_bfloat16 hi = __float2bfloat16_rn(v);
        __nv_bfloat16 lo = __float2bfloat16_rn(v - __bfloat162float(hi));
        Whi[(size_t)(n0 + n) * K + k0 + tx] = hi;
        Wlo[(size_t)(n0 + n) * K + k0 + tx] = lo;
    }
}

__global__ void prep_mask(const int* __restrict__ mask, float* __restrict__ mf) {
    int i = blockIdx.x * 256 + threadIdx.x;
    if (i < BB * SS) mf[i] = mask[i] ? 0.f : -1e30f;
}

// ---------------------------------------------------------------------------
// mma.sync GEMM (as round 4). MODE 0: scatter to Q/K/V hi/lo bf16 arrays.
// MODE 1: fp32 linear store to Cout.
// ---------------------------------------------------------------------------
#define KC 32
#define PITCH 80
#define TILE_BYTES (128 * PITCH)
#define BUF_BYTES (4 * TILE_BYTES)
#define GEMM_SMEM (2 * BUF_BYTES)

template<int MODE>
__global__ __launch_bounds__(256) void mma_gemm(
    const float* __restrict__ A,
    const __nv_bfloat16* __restrict__ Bhi,
    const __nv_bfloat16* __restrict__ Blo,
    const float* __restrict__ bias,
    float* __restrict__ Cout) {
    extern __shared__ char smem[];
    uint32_t smem_u = smem_to_u32(smem);
    int tid = threadIdx.x, wid = tid >> 5, lane = tid & 31;
    int m0 = blockIdx.y * 128, n0 = blockIdx.x * 128;
    int wm = (wid >> 2) * 64;
    int wn = (wid & 3) * 32;

    const int NCH = D_MODEL / KC;

    float4 pa[2][2];
    uint4  pbh[2], pbl[2];
    int arow[2], au[2], brow[2], bu[2];
#pragma unroll
    for (int it = 0; it < 2; it++) {
        int idx = tid + it * 256;
        arow[it] = idx >> 2; au[it] = idx & 3;
        brow[it] = idx >> 2; bu[it] = idx & 3;
    }

    auto ldg_chunk = [&](int c) {
        int k0 = c * KC;
#pragma unroll
        for (int it = 0; it < 2; it++) {
            const float* ap = A + (size_t)(m0 + arow[it]) * D_MODEL + k0 + au[it] * 8;
            pa[it][0] = *(const float4*)ap;
            pa[it][1] = *(const float4*)(ap + 4);
            pbh[it] = *(const uint4*)(Bhi + (size_t)(n0 + brow[it]) * D_MODEL + k0 + bu[it] * 8);
            pbl[it] = *(const uint4*)(Blo + (size_t)(n0 + brow[it]) * D_MODEL + k0 + bu[it] * 8);
        }
    };
    auto sts_chunk = [&](int buf) {
        char* base = smem + buf * BUF_BYTES;
#pragma unroll
        for (int it = 0; it < 2; it++) {
            float4 x0 = pa[it][0], x1 = pa[it][1];
            __nv_bfloat162 h01 = __floats2bfloat162_rn(x0.x, x0.y);
            __nv_bfloat162 h23 = __floats2bfloat162_rn(x0.z, x0.w);
            __nv_bfloat162 h45 = __floats2bfloat162_rn(x1.x, x1.y);
            __nv_bfloat162 h67 = __floats2bfloat162_rn(x1.z, x1.w);
            __nv_bfloat162 l01 = __floats2bfloat162_rn(x0.x - __low2float(h01), x0.y - __high2float(h01));
            __nv_bfloat162 l23 = __floats2bfloat162_rn(x0.z - __low2float(h23), x0.w - __high2float(h23));
            __nv_bfloat162 l45 = __floats2bfloat162_rn(x1.x - __low2float(h45), x1.y - __high2float(h45));
            __nv_bfloat162 l67 = __floats2bfloat162_rn(x1.z - __low2float(h67), x1.w - __high2float(h67));
            uint32_t off = arow[it] * PITCH + au[it] * 16;
            *(uint4*)(base + off) = make_uint4(bf2u(h01), bf2u(h23), bf2u(h45), bf2u(h67));
            *(uint4*)(base + TILE_BYTES + off) = make_uint4(bf2u(l01), bf2u(l23), bf2u(l45), bf2u(l67));
            uint32_t boff = brow[it] * PITCH + bu[it] * 16;
            *(uint4*)(base + 2 * TILE_BYTES + boff) = pbh[it];
            *(uint4*)(base + 3 * TILE_BYTES + boff) = pbl[it];
        }
    };

    float acc[4][4][4];
#pragma unroll
    for (int i = 0; i < 4; i++)
#pragma unroll
        for (int j = 0; j < 4; j++)
#pragma unroll
            for (int r = 0; r < 4; r++) acc[i][j][r] = 0.f;

    ldg_chunk(0);
    sts_chunk(0);
    __syncthreads();

    int alr = lane & 15, alu = lane >> 4;
    int blr = (lane & 7) + ((lane >> 4) << 3);
    int blu = (lane >> 3) & 1;

    for (int c = 0; c < NCH; c++) {
        if (c + 1 < NCH) ldg_chunk(c + 1);

        uint32_t sA = smem_u + (c & 1) * BUF_BYTES;
        uint32_t sB = sA + 2 * TILE_BYTES;
#pragma unroll
        for (int ks = 0; ks < 2; ks++) {
            uint32_t ah[4][4], al[4][4], bh[4][2], bl[4][2];
#pragma unroll
            for (int fm = 0; fm < 4; fm++) {
                uint32_t ad = sA + (wm + fm * 16 + alr) * PITCH + (ks * 2 + alu) * 16;
                LDSM_X4(ah[fm][0], ah[fm][1], ah[fm][2], ah[fm][3], ad);
                LDSM_X4(al[fm][0], al[fm][1], al[fm][2], al[fm][3], ad + TILE_BYTES);
            }
#pragma unroll
            for (int fp = 0; fp < 2; fp++) {
                uint32_t bd = sB + (wn + fp * 16 + blr) * PITCH + (ks * 2 + blu) * 16;
                uint32_t r0, r1, r2, r3;
                LDSM_X4(r0, r1, r2, r3, bd);
                bh[fp * 2][0] = r0; bh[fp * 2][1] = r1;
                bh[fp * 2 + 1][0] = r2; bh[fp * 2 + 1][1] = r3;
                LDSM_X4(r0, r1, r2, r3, bd + TILE_BYTES);
                bl[fp * 2][0] = r0; bl[fp * 2][1] = r1;
                bl[fp * 2 + 1][0] = r2; bl[fp * 2 + 1][1] = r3;
            }
#pragma unroll
            for (int fm = 0; fm < 4; fm++)
#pragma unroll
                for (int fn = 0; fn < 4; fn++) {
                    MMA_BF16(acc[fm][fn], ah[fm], bh[fn][0], bh[fn][1]);
                    MMA_BF16(acc[fm][fn], ah[fm], bl[fn][0], bl[fn][1]);
                    MMA_BF16(acc[fm][fn], al[fm], bh[fn][0], bh[fn][1]);
                }
        }
        __syncthreads();
        if (c + 1 < NCH) {
            sts_chunk((c + 1) & 1);
            __syncthreads();
        }
    }

#pragma unroll
    for (int fm = 0; fm < 4; fm++)
#pragma unroll
        for (int fn = 0; fn < 4; fn++) {
            int gn = n0 + wn + fn * 8 + (lane & 3) * 2;
            float bx = bias[gn], by = bias[gn + 1];
#pragma unroll
            for (int half = 0; half < 2; half++) {
                int gm = m0 + wm + fm * 16 + (lane >> 2) + half * 8;
                float2 v = make_float2(acc[fm][fn][half * 2] + bx,
                                       acc[fm][fn][half * 2 + 1] + by);
                if (MODE == 0) {
                    int bb = gm >> 11, ssi = gm & 2047;
                    int sel = gn >> 10, d = gn & 1023;
                    int hh = d >> 6, dd = d & 63;
                    __nv_bfloat16 *dh_, *dl_;
                    if (sel == 0)      { dh_ = g_Qh; dl_ = g_Ql; }
                    else if (sel == 1) { dh_ = g_Kh; dl_ = g_Kl; }
                    else               { dh_ = g_Vh; dl_ = g_Vl; }
                    size_t off = ((size_t)(bb * NHEAD + hh) * SS + ssi) * DH + dd;
                    __nv_bfloat162 hi = __floats2bfloat162_rn(v.x, v.y);
                    __nv_bfloat162 lo = __floats2bfloat162_rn(v.x - __low2float(hi),
                                                              v.y - __high2float(hi));
                    *(__nv_bfloat162*)(dh_ + off) = hi;
                    *(__nv_bfloat162*)(dl_ + off) = lo;
                } else {
                    *(float2*)(Cout + (size_t)gm * D_MODEL + gn) = v;
                }
            }
        }
}

// ---------------------------------------------------------------------------
// Flash attention on tensor cores (mma.sync bf16, 3-MMA hi/lo split both for
// QK^T and PV). Q-tile 128 x K-tile 64, 8 warps (16 q-rows each).
// K/V streamed by cp.async double buffering; smem pitch 144B (conflict-free).
// ---------------------------------------------------------------------------
#define AP 144                     // smem pitch bytes (64 bf16 data + 8 pad)
#define SQH 0
#define SQL 18432                  // 128*144
#define SKV 36864
#define KVS 36864                  // per-buffer: Kh,Kl,Vh,Vl each 64*144=9216
#define ATTN_SMEM (SKV + 2*KVS)    // 110592

__global__ __launch_bounds__(256, 1) void attn_mma(const float* __restrict__ maskf) {
    extern __shared__ char sm[];
    uint32_t su = smem_to_u32(sm);
    int tid = threadIdx.x, lane = tid & 31, wid = tid >> 5;
    int qt = blockIdx.x, bh = blockIdx.y, b = bh >> 4, h = bh & 15;

    const char* qh_g = (const char*)(g_Qh + ((size_t)bh * SS + qt * 128) * DH);
    const char* ql_g = (const char*)(g_Ql + ((size_t)bh * SS + qt * 128) * DH);
    const char* kh_g = (const char*)(g_Kh + (size_t)bh * SS * DH);
    const char* kl_g = (const char*)(g_Kl + (size_t)bh * SS * DH);
    const char* vh_g = (const char*)(g_Vh + (size_t)bh * SS * DH);
    const char* vl_g = (const char*)(g_Vl + (size_t)bh * SS * DH);

    // prologue: Q (both halves) + KV tile 0 -> group 0
#pragma unroll
    for (int it = 0; it < 4; it++) {
        int c = tid + it * 256;           // 1024 chunks of 16B per array
        int row = c >> 3, u = c & 7;
        uint32_t so = row * AP + u * 16;
        uint32_t go = row * 128 + u * 16;
        CP_ASYNC16(su + SQH + so, qh_g + go);
        CP_ASYNC16(su + SQL + so, ql_g + go);
    }
#pragma unroll
    for (int it = 0; it < 2; it++) {
        int c = tid + it * 256;           // 512 chunks per array
        int row = c >> 3, u = c & 7;
        uint32_t so = row * AP + u * 16;
        uint32_t go = row * 128 + u * 16;
        CP_ASYNC16(su + SKV + so,         kh_g + go);
        CP_ASYNC16(su + SKV + 9216 + so,  kl_g + go);
        CP_ASYNC16(su + SKV + 18432 + so, vh_g + go);
        CP_ASYNC16(su + SKV + 27648 + so, vl_g + go);
    }
    CP_COMMIT();

    float m0 = -1e30f, m1 = -1e30f, l0 = 0.f, l1 = 0.f;
    float o[8][4];
#pragma unroll
    for (int i = 0; i < 8; i++)
#pragma unroll
        for (int j = 0; j < 4; j++) o[i][j] = 0.f;

    uint32_t qfh[4][4], qfl[4][4];
    int alr = lane & 15, alu = lane >> 4;
    int blr = (lane & 7) + ((lane >> 4) << 3), blu = (lane >> 3) & 1;
    int vt = lane >> 3, vr = lane & 7;

    for (int kt = 0; kt < SS / 64; kt++) {
        __syncthreads();   // everyone done reading the buffer we refill next
        if (kt + 1 < SS / 64) {
            uint32_t base = su + SKV + ((kt + 1) & 1) * KVS;
            size_t gt = (size_t)(kt + 1) * 64 * 128;   // bytes per KV tile
#pragma unroll
            for (int it = 0; it < 2; it++) {
                int c = tid + it * 256;
                int row = c >> 3, u = c & 7;
                uint32_t so = row * AP + u * 16;
                size_t go = gt + row * 128 + u * 16;
                CP_ASYNC16(base + so,         kh_g + go);
                CP_ASYNC16(base + 9216 + so,  kl_g + go);
                CP_ASYNC16(base + 18432 + so, vh_g + go);
                CP_ASYNC16(base + 27648 + so, vl_g + go);
            }
        }
        CP_COMMIT();
        CP_WAIT1();
        __syncthreads();

        uint32_t cb = su + SKV + (kt & 1) * KVS;

        if (kt == 0) {
#pragma unroll
            for (int ks = 0; ks < 4; ks++) {
                uint32_t a = su + SQH + (wid * 16 + alr) * AP + (ks * 2 + alu) * 16;
                LDSM_X4(qfh[ks][0], qfh[ks][1], qfh[ks][2], qfh[ks][3], a);
                LDSM_X4(qfl[ks][0], qfl[ks][1], qfl[ks][2], qfl[ks][3], a + (SQL - SQH));
            }
        }

        // ---- S = Q K^T (hi/lo split) ----
        float s[8][4];
#pragma unroll
        for (int i = 0; i < 8; i++)
#pragma unroll
            for (int j = 0; j < 4; j++) s[i][j] = 0.f;

#pragma unroll
        for (int ks = 0; ks < 4; ks++) {
            uint32_t kh[8][2], kl2[8][2];
#pragma unroll
            for (int fp = 0; fp < 4; fp++) {
                uint32_t ad = cb + (fp * 16 + blr) * AP + (ks * 2 + blu) * 16;
                uint32_t r0, r1, r2, r3;
                LDSM_X4(r0, r1, r2, r3, ad);
                kh[fp * 2][0] = r0; kh[fp * 2][1] = r1;
                kh[fp * 2 + 1][0] = r2; kh[fp * 2 + 1][1] = r3;
                LDSM_X4(r0, r1, r2, r3, ad + 9216);
                kl2[fp * 2][0] = r0; kl2[fp * 2][1] = r1;
                kl2[fp * 2 + 1][0] = r2; kl2[fp * 2 + 1][1] = r3;
            }
#pragma unroll
            for (int nf = 0; nf < 8; nf++) {
                MMA_BF16(s[nf], qfh[ks], kh[nf][0], kh[nf][1]);
                MMA_BF16(s[nf], qfh[ks], kl2[nf][0], kl2[nf][1]);
                MMA_BF16(s[nf], qfl[ks], kh[nf][0], kh[nf][1]);
            }
        }

        // ---- mask + scale + online softmax (rows r0=lane>>2, r1=r0+8) ----
        const float* mrow = maskf + b * SS + kt * 64;
        float rx0 = -1e30f, rx1 = -1e30f;
#pragma unroll
        for (int nf = 0; nf < 8; nf++) {
            float2 mk = *(const float2*)(mrow + nf * 8 + (lane & 3) * 2);
            s[nf][0] = fmaf(s[nf][0], 0.125f, mk.x);
            s[nf][1] = fmaf(s[nf][1], 0.125f, mk.y);
            s[nf][2] = fmaf(s[nf][2], 0.125f, mk.x);
            s[nf][3] = fmaf(s[nf][3], 0.125f, mk.y);
            rx0 = fmaxf(rx0, fmaxf(s[nf][0], s[nf][1]));
            rx1 = fmaxf(rx1, fmaxf(s[nf][2], s[nf][3]));
        }
        rx0 = fmaxf(rx0, __shfl_xor_sync(0xffffffffu, rx0, 1));
        rx0 = fmaxf(rx0, __shfl_xor_sync(0xffffffffu, rx0, 2));
        rx1 = fmaxf(rx1, __shfl_xor_sync(0xffffffffu, rx1, 1));
        rx1 = fmaxf(rx1, __shfl_xor_sync(0xffffffffu, rx1, 2));
        float mn0 = fmaxf(m0, rx0), mn1 = fmaxf(m1, rx1);
        float c0 = fast_exp(m0 - mn0), c1 = fast_exp(m1 - mn1);
        m0 = mn0; m1 = mn1;

        float rs0 = 0.f, rs1 = 0.f;
        uint32_t pAh[8], pBh[8], pAl[8], pBl[8];
#pragma unroll
        for (int nf = 0; nf < 8; nf++) {
            float p0 = fast_exp(s[nf][0] - mn0), p1 = fast_exp(s[nf][1] - mn0);
            float p2 = fast_exp(s[nf][2] - mn1), p3 = fast_exp(s[nf][3] - mn1);
            rs0 += p0 + p1; rs1 += p2 + p3;
            __nv_bfloat162 h01 = __floats2bfloat162_rn(p0, p1);
            __nv_bfloat162 h23 = __floats2bfloat162_rn(p2, p3);
            __nv_bfloat162 l01 = __floats2bfloat162_rn(p0 - __low2float(h01), p1 - __high2float(h01));
            __nv_bfloat162 l23 = __floats2bfloat162_rn(p2 - __low2float(h23), p3 - __high2float(h23));
            pAh[nf] = bf2u(h01); pBh[nf] = bf2u(h23);
            pAl[nf] = bf2u(l01); pBl[nf] = bf2u(l23);
        }
        rs0 += __shfl_xor_sync(0xffffffffu, rs0, 1);
        rs0 += __shfl_xor_sync(0xffffffffu, rs0, 2);
        rs1 += __shfl_xor_sync(0xffffffffu, rs1, 1);
        rs1 += __shfl_xor_sync(0xffffffffu, rs1, 2);
        l0 = l0 * c0 + rs0; l1 = l1 * c1 + rs1;
#pragma unroll
        for (int nf = 0; nf < 8; nf++) {
            o[nf][0] *= c0; o[nf][1] *= c0; o[nf][2] *= c1; o[nf][3] *= c1;
        }

        // ---- O += P V (hi/lo split), V via ldmatrix.trans ----
#pragma unroll
        for (int ks = 0; ks < 4; ks++) {
            uint32_t ah[4]  = { pAh[2 * ks], pBh[2 * ks], pAh[2 * ks + 1], pBh[2 * ks + 1] };
            uint32_t al2[4] = { pAl[2 * ks], pBl[2 * ks], pAl[2 * ks + 1], pBl[2 * ks + 1] };
#pragma unroll
            for (int nb = 0; nb < 4; nb++) {
                uint32_t va = cb + 18432 + (ks * 16 + (vt & 1) * 8 + vr) * AP
                              + nb * 32 + (vt >> 1) * 16;
                uint32_t h0, h1, h2, h3, w0, w1, w2, w3;
                LDSM_X4_T(h0, h1, h2, h3, va);
                LDSM_X4_T(w0, w1, w2, w3, va + 9216);
                MMA_BF16(o[2 * nb],     ah,  h0, h1);
                MMA_BF16(o[2 * nb],     ah,  w0, w1);
                MMA_BF16(o[2 * nb],     al2, h0, h1);
                MMA_BF16(o[2 * nb + 1], ah,  h2, h3);
                MMA_BF16(o[2 * nb + 1], ah,  w2, w3);
                MMA_BF16(o[2 * nb + 1], al2, h2, h3);
            }
        }
    }

    // ---- epilogue ----
    float i0 = 1.f / l0, i1 = 1.f / l1;
    int r0 = qt * 128 + wid * 16 + (lane >> 2), r1 = r0 + 8;
#pragma unroll
    for (int nf = 0; nf < 8; nf++) {
        int col = h * DH + nf * 8 + (lane & 3) * 2;
        *(float2*)(g_attn + (size_t)(b * SS + r0) * D_MODEL + col) =
            make_float2(o[nf][0] * i0, o[nf][1] * i0);
        *(float2*)(g_attn + (size_t)(b * SS + r1) * D_MODEL + col) =
            make_float2(o[nf][2] * i1, o[nf][3] * i1);
    }
}

extern "C" void kernel_launch(void* const* d_in, const int* in_sizes, int n_in,
                              void* d_out, int out_size) {
    const float* x    = (const float*)d_in[0];
    const int*   mask = (const int*)d_in[1];
    const float* Wqkv = (const float*)d_in[2];
    const float* bqkv = (const float*)d_in[3];
    const float* Wout = (const float*)d_in[4];
    const float* bout = (const float*)d_in[5];
    float*       out  = (float*)d_out;

    __nv_bfloat16 *wqh, *wql, *woh, *wol;
    cudaGetSymbolAddress((void**)&wqh, g_Wqkv_hi);
    cudaGetSymbolAddress((void**)&wql, g_Wqkv_lo);
    cudaGetSymbolAddress((void**)&woh, g_Wout_hi);
    cudaGetSymbolAddress((void**)&wol, g_Wout_lo);
    float *gattn, *gmaskf;
    cudaGetSymbolAddress((void**)&gattn, g_attn);
    cudaGetSymbolAddress((void**)&gmaskf, g_maskf);

    // 1) weight transpose + bf16 hi/lo split; mask -> float bias
    split_w<<<dim3(QKV_N / 32, D_MODEL / 32), 256>>>(Wqkv, wqh, wql, D_MODEL, QKV_N);
    split_w<<<dim3(D_MODEL / 32, D_MODEL / 32), 256>>>(Wout, woh, wol, D_MODEL, D_MODEL);
    prep_mask<<<(BB * SS + 255) / 256, 256>>>(mask, gmaskf);

    // 2) QKV projection (tensor cores) -> pre-split bf16 Q/K/V
    cudaFuncSetAttribute(mma_gemm<0>, cudaFuncAttributeMaxDynamicSharedMemorySize, GEMM_SMEM);
    cudaFuncSetAttribute(mma_gemm<1>, cudaFuncAttributeMaxDynamicSharedMemorySize, GEMM_SMEM);
    mma_gemm<0><<<dim3(QKV_N / 128, M_TOT / 128), 256, GEMM_SMEM>>>(x, wqh, wql, bqkv, nullptr);

    // 3) attention on tensor cores
    cudaFuncSetAttribute(attn_mma, cudaFuncAttributeMaxDynamicSharedMemorySize, ATTN_SMEM);
    attn_mma<<<dim3(SS / 128, BB * NHEAD), 256, ATTN_SMEM>>>(gmaskf);

    // 4) output projection (tensor cores)
    mma_gemm<1><<<dim3(D_MODEL / 128, M_TOT / 128), 256, GEMM_SMEM>>>(gattn, woh, wol, bout, out);
}